// round 4
// baseline (speedup 1.0000x reference)
#include <cuda_runtime.h>

#define NN 307
#define DD 64
#define EE 4912
#define TT 288
#define BB 8
#define G  148   // persistent grid size; <= SM count (B300:148, GB300:152) => co-resident

// ---- scratch (device globals; no allocation allowed) ----
__device__ float    g_p[NN * DD];      // projected features p = h @ W
__device__ float    g_ss[NN * 8];      // per-node src scores
__device__ float    g_st[NN * 8];      // per-node tgt scores
__device__ float    g_num[NN * DD];    // softmax-weighted numerator accum
__device__ float    g_den[NN * 8];     // softmax denominator accum
__device__ float    g_hout[NN * DD];   // final GAT output (read by k_big)
__device__ float    g_c[TT * DD];      // pe[t,d] + b_val[d]
__device__ unsigned g_barc[8];         // grid-barrier counters (zeroed by k_init)

// --------------------------------------------------------------------------
// Software grid barrier. All G blocks co-resident (occ=1 guaranteed by size).
// Release: __threadfence before arrival drains prior STG to L2.
// Acquire: __threadfence after spin emits CCTL.IVALL -> invalidates this SM's
// L1 so post-barrier loads see other blocks' writes.
// --------------------------------------------------------------------------
__device__ __forceinline__ void gbar(int i)
{
    __syncthreads();
    if (threadIdx.x == 0) {
        __threadfence();
        atomicAdd(&g_barc[i], 1u);
        while (*((volatile unsigned*)&g_barc[i]) < (unsigned)G) {}
        __threadfence();
    }
    __syncthreads();
}

// --------------------------------------------------------------------------
// Per-node projection + attention scores. Node n handled by 64 threads
// (sub = tid>>6 selects which of the block's 4 nodes). Writes p/ss/st to
// global for the edge phase; zeroes the accumulators for this layer.
// --------------------------------------------------------------------------
template<int H, int F>
__device__ __forceinline__ void proj_scores(bool act, int n, int sub, int lane,
                                            const float* __restrict__ W,
                                            const float* __restrict__ as,
                                            const float* __restrict__ at,
                                            float (*sh)[DD], float (*sp)[DD])
{
    if (act) {
        float p = 0.f;
#pragma unroll
        for (int k = 0; k < DD; k++)
            p += sh[sub][k] * W[k * DD + lane];
        g_p[n * DD + lane]   = p;
        g_num[n * DD + lane] = 0.f;
        sp[sub][lane] = p;
    }
    __syncthreads();
    if (act && lane < H) {
        float ssv = 0.f, stv = 0.f;
#pragma unroll
        for (int f = 0; f < F; f++) {
            float v = sp[sub][lane * F + f];
            ssv += v * as[lane * F + f];
            stv += v * at[lane * F + f];
        }
        g_ss[n * H + lane]  = ssv;
        g_st[n * H + lane]  = stv;
        g_den[n * H + lane] = 0.f;
    }
    __syncthreads();
}

// --------------------------------------------------------------------------
// Edge phase: w = exp(leaky_relu(ss[src]+st[tgt])); num[tgt]+=w*p[src];
// den[tgt]+=w. Max-subtraction dropped (activations are O(0.1); identical
// math, validated at rel_err 1.1e-6 in R2). __ldcg: bypass stale L1.
// --------------------------------------------------------------------------
template<int H, int F>
__device__ __forceinline__ void edge_phase(const int* __restrict__ ei)
{
    for (int idx = blockIdx.x * blockDim.x + threadIdx.x;
         idx < EE * DD; idx += G * 256) {
        int e = idx >> 6;
        int d = idx & 63;
        int h = d / F;                      // compile-time F -> shift
        int s = __ldg(&ei[e]);
        int t = __ldg(&ei[EE + e]);
        float ev = __ldcg(&g_ss[s * H + h]) + __ldcg(&g_st[t * H + h]);
        ev = ev > 0.f ? ev : 0.2f * ev;
        float w = __expf(ev);
        if ((d % F) == 0) atomicAdd(&g_den[t * H + h], w);
        atomicAdd(&g_num[t * DD + d], w * __ldcg(&g_p[s * DD + d]));
    }
}

// --------------------------------------------------------------------------
// Finalize: h_next = act(num/(den+eps) + skip + b). h stays in shared.
// --------------------------------------------------------------------------
template<int H, int F, bool IDENT, bool LAST>
__device__ __forceinline__ void fin(bool act, int n, int sub, int lane,
                                    const float* __restrict__ skipW,
                                    const float* __restrict__ b,
                                    float (*sh)[DD])
{
    float v = 0.f;
    if (act) {
        float num = __ldcg(&g_num[n * DD + lane]);
        float den = __ldcg(&g_den[n * H + lane / F]);
        v = num / (den + 1e-16f);
        float skip;
        if (IDENT) {
            skip = sh[sub][lane];
        } else {
            skip = 0.f;
#pragma unroll
            for (int k = 0; k < DD; k++)
                skip += sh[sub][k] * skipW[k * DD + lane];
        }
        v += skip + b[lane];
        if (!LAST) v = v > 0.f ? v : (__expf(v) - 1.f);   // ELU
    }
    __syncthreads();              // done reading old sh
    if (act) sh[sub][lane] = v;
    __syncthreads();
}

// --------------------------------------------------------------------------
// Whole 3-layer GAT in one persistent kernel. Each block owns 4 fixed nodes
// for all per-node phases; h lives in shared across layers.
// --------------------------------------------------------------------------
__global__ void __launch_bounds__(256, 1)
k_gat(const float* __restrict__ node_f, const int* __restrict__ ei,
      const float* __restrict__ W_sta, const float* __restrict__ b_sta,
      const float* __restrict__ ada,
      const float* __restrict__ g0W, const float* __restrict__ g0as,
      const float* __restrict__ g0at, const float* __restrict__ g0b,
      const float* __restrict__ g1W, const float* __restrict__ g1as,
      const float* __restrict__ g1at, const float* __restrict__ g1b,
      const float* __restrict__ g2W, const float* __restrict__ g2as,
      const float* __restrict__ g2at, const float* __restrict__ g2b,
      const float* __restrict__ g0skip, const float* __restrict__ g1skip)
{
    __shared__ float sh[4][DD];   // current h, persists across layers
    __shared__ float sp[4][DD];

    int tid  = threadIdx.x;
    int sub  = tid >> 6;
    int lane = tid & 63;
    int n    = blockIdx.x * 4 + sub;
    bool act = n < NN;

    // node-feature embedding: nf = node_f @ W_sta + b_sta + ada
    if (act) {
        float acc = b_sta[lane] + ada[n * DD + lane];
#pragma unroll
        for (int k = 0; k < 32; k++)
            acc += node_f[n * 32 + k] * W_sta[k * DD + lane];
        sh[sub][lane] = acc;
    }
    __syncthreads();

    // ---- layer 0 ----
    proj_scores<8, 8>(act, n, sub, lane, g0W, g0as, g0at, sh, sp);
    gbar(0);
    edge_phase<8, 8>(ei);
    gbar(1);
    fin<8, 8, false, false>(act, n, sub, lane, g0skip, g0b, sh);

    // ---- layer 1 ----
    proj_scores<8, 8>(act, n, sub, lane, g1W, g1as, g1at, sh, sp);
    gbar(2);
    edge_phase<8, 8>(ei);
    gbar(3);
    fin<8, 8, false, false>(act, n, sub, lane, g1skip, g1b, sh);

    // ---- layer 2 (H=1, F=64, identity skip, no activation) ----
    proj_scores<1, 64>(act, n, sub, lane, g2W, g2as, g2at, sh, sp);
    gbar(4);
    edge_phase<1, 64>(ei);
    gbar(5);
    fin<1, 64, true, true>(act, n, sub, lane, nullptr, g2b, sh);

    if (act) g_hout[n * DD + lane] = sh[sub][lane];
}

// --------------------------------------------------------------------------
// Init: zero barrier counters + build c[t,d] = PE(t,d) + b_val[d]
// --------------------------------------------------------------------------
__global__ void k_init(const float* __restrict__ b_val)
{
    int idx = blockIdx.x * blockDim.x + threadIdx.x;
    if (idx < 8) g_barc[idx] = 0u;
    if (idx < TT * DD) {
        int t = idx / DD;
        int d = idx % DD;
        float freq = __expf((float)(d & ~1) * (-9.210340371976184f / 64.0f));
        float ang  = (float)t * freq;
        float pe   = (d & 1) ? cosf(ang) : sinf(ang);
        g_c[idx] = pe + b_val[d];
    }
}

// --------------------------------------------------------------------------
// Big broadcast kernel (the only HBM-heavy one):
// out[b,t,n,d] = x[b,t,n]*W_val[d] + c[t,d] + h[n,d], float4-vectorized.
// --------------------------------------------------------------------------
__global__ void k_big(const float* __restrict__ x,
                      const float* __restrict__ Wv,
                      float4* __restrict__ out, int total)
{
    int idx = blockIdx.x * blockDim.x + threadIdx.x;
    if (idx >= total) return;
    int dq   = idx & 15;
    int rest = idx >> 4;            // (b*T + t)*N + n
    int n    = rest % NN;
    int bt   = rest / NN;
    int t    = bt % TT;

    float xv = __ldg(&x[rest]);
    const float4 w  = ((const float4*)Wv)[dq];
    const float4 cc = ((const float4*)g_c)[t * 16 + dq];
    const float4 hh = ((const float4*)g_hout)[n * 16 + dq];

    float4 o;
    o.x = fmaf(xv, w.x, cc.x + hh.x);
    o.y = fmaf(xv, w.y, cc.y + hh.y);
    o.z = fmaf(xv, w.z, cc.z + hh.z);
    o.w = fmaf(xv, w.w, cc.w + hh.w);
    out[idx] = o;
}

extern "C" void kernel_launch(void* const* d_in, const int* in_sizes, int n_in,
                              void* d_out, int out_size)
{
    const float* x       = (const float*)d_in[0];
    const float* node_f  = (const float*)d_in[1];
    const int*   ei      = (const int*)d_in[2];
    // d_in[3] edge_prob unused
    const float* W_val   = (const float*)d_in[4];
    const float* b_val   = (const float*)d_in[5];
    const float* W_sta   = (const float*)d_in[6];
    const float* b_sta   = (const float*)d_in[7];
    const float* ada     = (const float*)d_in[8];
    const float* g0W     = (const float*)d_in[9];
    const float* g0as    = (const float*)d_in[10];
    const float* g0at    = (const float*)d_in[11];
    const float* g0b     = (const float*)d_in[12];
    const float* g1W     = (const float*)d_in[13];
    const float* g1as    = (const float*)d_in[14];
    const float* g1at    = (const float*)d_in[15];
    const float* g1b     = (const float*)d_in[16];
    const float* g2W     = (const float*)d_in[17];
    const float* g2as    = (const float*)d_in[18];
    const float* g2at    = (const float*)d_in[19];
    const float* g2b     = (const float*)d_in[20];
    const float* g0skip  = (const float*)d_in[21];
    const float* g1skip  = (const float*)d_in[22];

    // 1) barrier reset + PE table
    k_init<<<(TT * DD + 255) / 256, 256>>>(b_val);

    // 2) whole GAT in one persistent kernel
    k_gat<<<G, 256>>>(node_f, ei, W_sta, b_sta, ada,
                      g0W, g0as, g0at, g0b,
                      g1W, g1as, g1at, g1b,
                      g2W, g2as, g2at, g2b,
                      g0skip, g1skip);

    // 3) broadcast add (HBM-bound)
    int total = BB * TT * NN * 16;    // one thread per float4
    k_big<<<(total + 255) / 256, 256>>>(x, W_val, (float4*)d_out, total);
}